// round 13
// baseline (speedup 1.0000x reference)
#include <cuda_runtime.h>
#include <cuda_fp16.h>
#include <cstdint>

#define N_NODES 50000
#define DS 127
#define DPAD 128
#define NE 800000
#define EPSF 1e-7f
#define GR 64       // rows per gemm block
#define HSTRIDE 136 // smem stride in halves (conflict-free ldmatrix)

// g_x16: x as fp16, padded [N][128], pad col 0
// g_h16: h1 = relu(agg1)+x as fp16 (layer-2 prologue), pad col 0
// g_z  : gemm output fp16; pad col 0
// g_agg: aggregation result fp16 (written once per layer by k_agg); pad col 0
// g_Wt : W1,W2 as fp16, n-major [n][k] 128x128 each, pads zero
__device__ __align__(16) __half g_x16[N_NODES * DPAD];
__device__ __align__(16) __half g_h16[N_NODES * DPAD];
__device__ __align__(16) __half g_z[N_NODES * DPAD];
__device__ __align__(16) __half g_agg[N_NODES * DPAD];
__device__ __align__(16) __half g_Wt[2 * DPAD * DPAD];

// dst-sorted edge structures (built once per launch)
__device__ int   g_cnt[N_NODES];     // in-degree
__device__ int   g_off[N_NODES];     // exclusive prefix of g_cnt
__device__ int   g_fill[N_NODES];    // scatter cursors
__device__ int   g_src_s[NE];        // src sorted by dst
__device__ float g_w_s[NE];          // weight sorted by dst

__device__ __forceinline__ float warp_sum(float v) {
#pragma unroll
    for (int o = 16; o; o >>= 1) v += __shfl_xor_sync(0xffffffffu, v, o);
    return v;
}

__device__ __forceinline__ void ldsm4(uint32_t* r, uint32_t addr) {
    asm volatile("ldmatrix.sync.aligned.m8n8.x4.shared.b16 {%0,%1,%2,%3}, [%4];"
                 : "=r"(r[0]), "=r"(r[1]), "=r"(r[2]), "=r"(r[3]) : "r"(addr));
}

__device__ __forceinline__ void mma16816(float* c, const uint32_t* a,
                                         uint32_t b0, uint32_t b1) {
    asm volatile(
        "mma.sync.aligned.m16n8k16.row.col.f32.f16.f16.f32 "
        "{%0,%1,%2,%3}, {%4,%5,%6,%7}, {%8,%9}, {%0,%1,%2,%3};"
        : "+f"(c[0]), "+f"(c[1]), "+f"(c[2]), "+f"(c[3])
        : "r"(a[0]), "r"(a[1]), "r"(a[2]), "r"(a[3]), "r"(b0), "r"(b1));
}

// ---------------- prep: weights / x ----------------

__global__ void k_prepW(const float* __restrict__ W1, const float* __restrict__ W2) {
    int idx = blockIdx.x * 256 + threadIdx.x;
    if (idx >= 2 * DPAD * DPAD) return;
    int l = idx >> 14, rem = idx & 16383, n = rem >> 7, k = rem & 127;
    const float* W = l ? W2 : W1;
    float v = (k < DS && n < DS) ? W[k * DS + n] : 0.f;
    g_Wt[idx] = __float2half(v);
}

__global__ void k_prepX(const float* __restrict__ x) {
    int idx = blockIdx.x * 256 + threadIdx.x;
    if (idx >= N_NODES * DPAD) return;
    int row = idx >> 7, c = idx & 127;
    g_x16[idx] = __float2half((c < DS) ? x[row * DS + c] : 0.f);
}

// ---------------- edge sort by dst (counting sort) ----------------

__global__ void k_zero() {
    int i = blockIdx.x * 256 + threadIdx.x;
    if (i < N_NODES) g_cnt[i] = 0;
}

__global__ void k_hist(const int* __restrict__ dst) {
    int e = blockIdx.x * 256 + threadIdx.x;
    if (e < NE) atomicAdd(&g_cnt[dst[e]], 1);
}

// single block, 1024 threads: exclusive scan of g_cnt -> g_off; zero g_fill
__global__ void k_scan() {
    const int CH = (N_NODES + 1023) / 1024;   // 49
    int t = threadIdx.x;
    int start = t * CH;
    int sum = 0;
    for (int i = 0; i < CH; i++) {
        int idx = start + i;
        if (idx < N_NODES) sum += g_cnt[idx];
    }
    __shared__ int tot[1024];
    tot[t] = sum;
    __syncthreads();
    for (int off = 1; off < 1024; off <<= 1) {
        int v = (t >= off) ? tot[t - off] : 0;
        __syncthreads();
        tot[t] += v;
        __syncthreads();
    }
    int run = tot[t] - sum;   // exclusive prefix of this chunk
    for (int i = 0; i < CH; i++) {
        int idx = start + i;
        if (idx < N_NODES) {
            g_off[idx]  = run;
            g_fill[idx] = 0;
            run += g_cnt[idx];
        }
    }
}

__global__ void k_scatter(const int* __restrict__ src, const int* __restrict__ dst,
                          const float* __restrict__ wt) {
    int e = blockIdx.x * 256 + threadIdx.x;
    if (e >= NE) return;
    int d = dst[e];
    int pos = g_off[d] + atomicAdd(&g_fill[d], 1);
    g_src_s[pos] = src[e];
    g_w_s[pos]   = wt[e];
}

// ---------------- gemm ----------------

// z = half(h @ W + b) via HMMA.
// layer==0: h = x16.  layer==1: h = relu(agg) + x16 (== h1), stored fp16 to g_h16.
__global__ void __launch_bounds__(256, 3)
k_gemm(const float* __restrict__ b, int layer) {
    extern __shared__ __align__(16) char smem_raw[];
    __half* Wt  = (__half*)smem_raw;                 // [128][136]
    __half* Ht  = Wt + DPAD * HSTRIDE;               // [64][136]
    float*  b_s = (float*)(Ht + GR * HSTRIDE);       // [128]
    int tid  = threadIdx.x;
    int row0 = blockIdx.x * GR;

    {
        const uint4* src = (const uint4*)(g_Wt + layer * DPAD * DPAD);
        for (int j = tid; j < 2048; j += 256) {
            int n = j >> 4, kc = j & 15;
            *(uint4*)(Wt + n * HSTRIDE + kc * 8) = src[j];
        }
    }
    if (tid < DPAD) b_s[tid] = (tid < DS) ? b[tid] : 0.f;

    for (int j = tid; j < GR * 16; j += 256) {
        int r = j >> 4, ch = j & 15;
        int row = row0 + r;
        uint4 v = make_uint4(0u, 0u, 0u, 0u);
        if (row < N_NODES) {
            v = ((const uint4*)(g_x16 + (size_t)row * DPAD))[ch];
            if (layer) {
                uint4 a = ((const uint4*)(g_agg + (size_t)row * DPAD))[ch];
                __half2* vh = (__half2*)&v;
                __half2* ah = (__half2*)&a;
#pragma unroll
                for (int i = 0; i < 4; i++) {
                    float2 xf = __half22float2(vh[i]);
                    float2 af = __half22float2(ah[i]);
                    vh[i] = __floats2half2_rn(xf.x + fmaxf(af.x, 0.f),
                                              xf.y + fmaxf(af.y, 0.f));
                }
                ((uint4*)(g_h16 + (size_t)row * DPAD))[ch] = v;
            }
        }
        *(uint4*)(Ht + r * HSTRIDE + ch * 8) = v;
    }
    __syncthreads();

    int lane = tid & 31, wid = tid >> 5;
    int wm = wid >> 2, wn = wid & 3;

    uint32_t ht_s = (uint32_t)__cvta_generic_to_shared(Ht);
    uint32_t wt_s = (uint32_t)__cvta_generic_to_shared(Wt);
    uint32_t aaddr[2];
#pragma unroll
    for (int mt = 0; mt < 2; mt++) {
        int rowA = wm * 32 + mt * 16 + (lane & 15);
        int kA   = (lane >> 4) * 8;
        aaddr[mt] = ht_s + (uint32_t)(rowA * HSTRIDE + kA) * 2;
    }
    uint32_t baddr[2];
#pragma unroll
    for (int p = 0; p < 2; p++) {
        int rowB = wn * 32 + p * 16 + (lane >> 4) * 8 + (lane & 7);
        int kB   = ((lane >> 3) & 1) * 8;
        baddr[p] = wt_s + (uint32_t)(rowB * HSTRIDE + kB) * 2;
    }

    float c[2][4][4];
#pragma unroll
    for (int mt = 0; mt < 2; mt++)
#pragma unroll
        for (int nt = 0; nt < 4; nt++)
#pragma unroll
            for (int j = 0; j < 4; j++) c[mt][nt][j] = 0.f;

#pragma unroll
    for (int ks = 0; ks < 8; ks++) {
        uint32_t kb = (uint32_t)(ks * 16 * 2);
        uint32_t a[2][4], bq[2][4];
        ldsm4(a[0], aaddr[0] + kb);
        ldsm4(a[1], aaddr[1] + kb);
        ldsm4(bq[0], baddr[0] + kb);
        ldsm4(bq[1], baddr[1] + kb);
#pragma unroll
        for (int mt = 0; mt < 2; mt++)
#pragma unroll
            for (int nt = 0; nt < 4; nt++)
                mma16816(c[mt][nt], a[mt], bq[nt >> 1][(nt & 1) * 2],
                         bq[nt >> 1][(nt & 1) * 2 + 1]);
    }

    int r_in = lane >> 2, col_in = 2 * (lane & 3);
#pragma unroll
    for (int mt = 0; mt < 2; mt++) {
#pragma unroll
        for (int nt = 0; nt < 4; nt++) {
            int row = row0 + wm * 32 + mt * 16 + r_in;
            int col = wn * 32 + nt * 8 + col_in;
            float bb0 = b_s[col], bb1 = b_s[col + 1];
            if (row < N_NODES)
                *(__half2*)(g_z + (size_t)row * DPAD + col) =
                    __floats2half2_rn(c[mt][nt][0] + bb0, c[mt][nt][1] + bb1);
            if (row + 8 < N_NODES)
                *(__half2*)(g_z + (size_t)(row + 8) * DPAD + col) =
                    __floats2half2_rn(c[mt][nt][2] + bb0, c[mt][nt][3] + bb1);
        }
    }
}

// ---------------- aggregation: warp per dst, no atomics ----------------

// agg[d] = sum_{e: dst==d} w_e * z[src_e]; fp32 register accumulation,
// single fp16 write per row. Lane holds cols 4*lane..4*lane+3 (uint2 = 4 halves).
__global__ void k_agg() {
    int warp = (blockIdx.x * blockDim.x + threadIdx.x) >> 5;
    int lane = threadIdx.x & 31;
    if (warp >= N_NODES) return;
    int off = g_off[warp];
    int deg = g_cnt[warp];

    const uint2* z2 = (const uint2*)g_z;
    float a0 = 0.f, a1 = 0.f, a2 = 0.f, a3 = 0.f;

    int i = 0;
    for (; i + 4 <= deg; i += 4) {
        int   s0 = g_src_s[off + i],     s1 = g_src_s[off + i + 1];
        int   s2 = g_src_s[off + i + 2], s3 = g_src_s[off + i + 3];
        float w0 = g_w_s[off + i],       w1 = g_w_s[off + i + 1];
        float w2 = g_w_s[off + i + 2],   w3 = g_w_s[off + i + 3];
        uint2 v0 = z2[(size_t)s0 * 32 + lane];
        uint2 v1 = z2[(size_t)s1 * 32 + lane];
        uint2 v2 = z2[(size_t)s2 * 32 + lane];
        uint2 v3 = z2[(size_t)s3 * 32 + lane];
#define ACC(vv, ww) { \
        float2 fx = __half22float2(*(const __half2*)&(vv).x); \
        float2 fy = __half22float2(*(const __half2*)&(vv).y); \
        a0 += (ww) * fx.x; a1 += (ww) * fx.y; \
        a2 += (ww) * fy.x; a3 += (ww) * fy.y; }
        ACC(v0, w0) ACC(v1, w1) ACC(v2, w2) ACC(v3, w3)
    }
    for (; i < deg; i++) {
        int   s = g_src_s[off + i];
        float w = g_w_s[off + i];
        uint2 v = z2[(size_t)s * 32 + lane];
        ACC(v, w)
    }
#undef ACC

    __half2 o0 = __floats2half2_rn(a0, a1);
    __half2 o1 = __floats2half2_rn(a2, a3);
    uint2 o;
    o.x = *(unsigned*)&o0;
    o.y = *(unsigned*)&o1;
    ((uint2*)g_agg)[(size_t)warp * 32 + lane] = o;
}

// ---------------- final ----------------

// h2 = relu(agg2) + h1;  out = expmap0(h2)
__global__ void k_final(float* __restrict__ out) {
    int warp = (blockIdx.x * blockDim.x + threadIdx.x) >> 5;
    int lane = threadIdx.x & 31;
    if (warp >= N_NODES) return;
    float v[4];
    float n2 = 0.f;
#pragma unroll
    for (int j = 0; j < 4; j++) {
        int c = lane + 32 * j;
        float a  = __half2float(g_agg[warp * DPAD + c]);
        float hv = __half2float(g_h16[warp * DPAD + c]);
        v[j] = (c < DS) ? (fmaxf(a, 0.f) + hv) : 0.f;
        n2 += v[j] * v[j];
    }
    n2 = warp_sum(n2);
    float n = fmaxf(sqrtf(n2), EPSF);
    float t = coshf(n);
    float f = sinhf(n) / n;
    if (lane == 0) out[warp * DPAD] = t;
#pragma unroll
    for (int j = 0; j < 4; j++) {
        int c = lane + 32 * j;
        if (c < DS) out[warp * DPAD + 1 + c] = f * v[j];
    }
}

extern "C" void kernel_launch(void* const* d_in, const int* in_sizes, int n_in,
                              void* d_out, int out_size) {
    const float* x  = (const float*)d_in[0];
    const float* W1 = (const float*)d_in[1];
    const float* b1 = (const float*)d_in[2];
    const float* W2 = (const float*)d_in[3];
    const float* b2 = (const float*)d_in[4];
    const int*   es = (const int*)d_in[5];
    const int*   ed = (const int*)d_in[6];
    const float* ew = (const float*)d_in[7];
    float* out = (float*)d_out;

    const int smem_bytes = (DPAD * HSTRIDE + GR * HSTRIDE) * 2 + DPAD * 4;  // 52736
    cudaFuncSetAttribute(k_gemm, cudaFuncAttributeMaxDynamicSharedMemorySize, smem_bytes);

    int gemm_blocks = (N_NODES + GR - 1) / GR;       // 782
    int node_blocks = (N_NODES + 195) / 196;
    int row_blocks  = (N_NODES * 32 + 255) / 256;    // 6250 (warp per node)
    int e_blocks    = (NE + 255) / 256;              // 3125

    k_prepW<<<(2 * DPAD * DPAD + 255) / 256, 256>>>(W1, W2);
    k_prepX<<<(N_NODES * DPAD + 255) / 256, 256>>>(x);

    // dst-sorted edge list (once per launch)
    k_zero<<<node_blocks, 256>>>();
    k_hist<<<e_blocks, 256>>>(ed);
    k_scan<<<1, 1024>>>();
    k_scatter<<<e_blocks, 256>>>(es, ed, ew);

    k_gemm<<<gemm_blocks, 256, smem_bytes>>>(b1, 0);
    k_agg<<<row_blocks, 256>>>();

    k_gemm<<<gemm_blocks, 256, smem_bytes>>>(b2, 1);
    k_agg<<<row_blocks, 256>>>();

    k_final<<<row_blocks, 256>>>(out);
}

// round 14
// speedup vs baseline: 1.5221x; 1.5221x over previous
#include <cuda_runtime.h>
#include <cuda_fp16.h>
#include <cstdint>

#define N_NODES 50000
#define DS 127
#define DPAD 128
#define NE 800000
#define EPSF 1e-7f
#define GR 64       // rows per gemm block
#define HSTRIDE 136 // smem stride in halves (conflict-free ldmatrix)

// g_x16: x as fp16, padded [N][128], pad col 0
// g_h16: h1 = relu(agg1)+x as fp16 (layer-2 prologue), pad col 0
// g_z  : gemm output fp16; pad col 0
// g_agg: fp16 atomic accumulation target; pad col garbage, never read
// g_Wt : W1,W2 as fp16, n-major [n][k] 128x128 each, pads zero
__device__ __align__(16) __half g_x16[N_NODES * DPAD];
__device__ __align__(16) __half g_h16[N_NODES * DPAD];
__device__ __align__(16) __half g_z[N_NODES * DPAD];
__device__ __align__(16) __half g_agg[N_NODES * DPAD];
__device__ __align__(16) __half g_Wt[2 * DPAD * DPAD];

__device__ __forceinline__ float warp_sum(float v) {
#pragma unroll
    for (int o = 16; o; o >>= 1) v += __shfl_xor_sync(0xffffffffu, v, o);
    return v;
}

__device__ __forceinline__ void ldsm4(uint32_t* r, uint32_t addr) {
    asm volatile("ldmatrix.sync.aligned.m8n8.x4.shared.b16 {%0,%1,%2,%3}, [%4];"
                 : "=r"(r[0]), "=r"(r[1]), "=r"(r[2]), "=r"(r[3]) : "r"(addr));
}

__device__ __forceinline__ void mma16816(float* c, const uint32_t* a,
                                         uint32_t b0, uint32_t b1) {
    asm volatile(
        "mma.sync.aligned.m16n8k16.row.col.f32.f16.f16.f32 "
        "{%0,%1,%2,%3}, {%4,%5,%6,%7}, {%8,%9}, {%0,%1,%2,%3};"
        : "+f"(c[0]), "+f"(c[1]), "+f"(c[2]), "+f"(c[3])
        : "r"(a[0]), "r"(a[1]), "r"(a[2]), "r"(a[3]), "r"(b0), "r"(b1));
}

__device__ __forceinline__ void cp16(uint32_t smem_addr, const void* gptr) {
    asm volatile("cp.async.cg.shared.global [%0], [%1], 16;"
                 :: "r"(smem_addr), "l"(gptr));
}
__device__ __forceinline__ void cp_commit_wait() {
    asm volatile("cp.async.commit_group;");
    asm volatile("cp.async.wait_group 0;");
}

// Merged prep: W1,W2 -> g_Wt (fp16 n-major, zero pads), x -> g_x16 (fp16 padded)
__global__ void k_prep(const float* __restrict__ W1, const float* __restrict__ W2,
                       const float* __restrict__ x) {
    int idx = blockIdx.x * 256 + threadIdx.x;
    const int WTOT = 2 * DPAD * DPAD;
    if (idx < WTOT) {
        int l = idx >> 14, rem = idx & 16383, n = rem >> 7, k = rem & 127;
        const float* W = l ? W2 : W1;
        float v = (k < DS && n < DS) ? W[k * DS + n] : 0.f;
        g_Wt[idx] = __float2half(v);
    }
    int xi = idx - WTOT;
    if (xi >= 0 && xi < N_NODES * DPAD) {
        int row = xi >> 7, c = xi & 127;
        g_x16[xi] = __float2half((c < DS) ? x[row * DS + c] : 0.f);
    }
}

// z = half(h @ W + b) via HMMA; agg zeroed in epilogue.
// layer==0: h = x16 (copied via cp.async).  layer==1: h = relu(agg)+x16 (== h1) -> g_h16.
// 256 threads = 8 warps: warp (wm=wid>>2, wn=wid&3) = rows [wm*32,+32) x cols [wn*32,+32).
__global__ void __launch_bounds__(256, 3)
k_gemm(const float* __restrict__ b, int layer) {
    extern __shared__ __align__(16) char smem_raw[];
    __half* Wt  = (__half*)smem_raw;                 // [128][136]
    __half* Ht  = Wt + DPAD * HSTRIDE;               // [64][136]
    float*  b_s = (float*)(Ht + GR * HSTRIDE);       // [128]
    int tid  = threadIdx.x;
    int row0 = blockIdx.x * GR;

    uint32_t wt_s = (uint32_t)__cvta_generic_to_shared(Wt);
    uint32_t ht_s = (uint32_t)__cvta_generic_to_shared(Ht);

    // Wt fill via cp.async: 2048 x 16B chunks
    {
        const uint4* src = (const uint4*)(g_Wt + layer * DPAD * DPAD);
        for (int j = tid; j < 2048; j += 256) {
            int n = j >> 4, kc = j & 15;
            cp16(wt_s + (uint32_t)(n * HSTRIDE + kc * 8) * 2, src + j);
        }
    }
    if (tid < DPAD) b_s[tid] = (tid < DS) ? b[tid] : 0.f;

    // h tile: 64 rows x 16 uint4 chunks
    if (layer == 0) {
        for (int j = tid; j < GR * 16; j += 256) {
            int r = j >> 4, ch = j & 15;
            int row = row0 + r;
            uint32_t dstp = ht_s + (uint32_t)(r * HSTRIDE + ch * 8) * 2;
            if (row < N_NODES) {
                cp16(dstp, (const uint4*)(g_x16 + (size_t)row * DPAD) + ch);
            } else {
                *(uint4*)(Ht + r * HSTRIDE + ch * 8) = make_uint4(0u, 0u, 0u, 0u);
            }
        }
    } else {
        for (int j = tid; j < GR * 16; j += 256) {
            int r = j >> 4, ch = j & 15;
            int row = row0 + r;
            uint4 v = make_uint4(0u, 0u, 0u, 0u);
            if (row < N_NODES) {
                v = ((const uint4*)(g_x16 + (size_t)row * DPAD))[ch];
                uint4 a = ((const uint4*)(g_agg + (size_t)row * DPAD))[ch];
                __half2* vh = (__half2*)&v;
                __half2* ah = (__half2*)&a;
#pragma unroll
                for (int i = 0; i < 4; i++) {
                    float2 xf = __half22float2(vh[i]);
                    float2 af = __half22float2(ah[i]);
                    vh[i] = __floats2half2_rn(xf.x + fmaxf(af.x, 0.f),
                                              xf.y + fmaxf(af.y, 0.f));
                }
                ((uint4*)(g_h16 + (size_t)row * DPAD))[ch] = v;
            }
            *(uint4*)(Ht + r * HSTRIDE + ch * 8) = v;
        }
    }
    cp_commit_wait();
    __syncthreads();

    int lane = tid & 31, wid = tid >> 5;
    int wm = wid >> 2, wn = wid & 3;

    uint32_t aaddr[2];
#pragma unroll
    for (int mt = 0; mt < 2; mt++) {
        int rowA = wm * 32 + mt * 16 + (lane & 15);
        int kA   = (lane >> 4) * 8;
        aaddr[mt] = ht_s + (uint32_t)(rowA * HSTRIDE + kA) * 2;
    }
    uint32_t baddr[2];
#pragma unroll
    for (int p = 0; p < 2; p++) {
        int rowB = wn * 32 + p * 16 + (lane >> 4) * 8 + (lane & 7);
        int kB   = ((lane >> 3) & 1) * 8;
        baddr[p] = wt_s + (uint32_t)(rowB * HSTRIDE + kB) * 2;
    }

    float c[2][4][4];
#pragma unroll
    for (int mt = 0; mt < 2; mt++)
#pragma unroll
        for (int nt = 0; nt < 4; nt++)
#pragma unroll
            for (int j = 0; j < 4; j++) c[mt][nt][j] = 0.f;

#pragma unroll
    for (int ks = 0; ks < 8; ks++) {
        uint32_t kb = (uint32_t)(ks * 16 * 2);
        uint32_t a[2][4], bq[2][4];
        ldsm4(a[0], aaddr[0] + kb);
        ldsm4(a[1], aaddr[1] + kb);
        ldsm4(bq[0], baddr[0] + kb);
        ldsm4(bq[1], baddr[1] + kb);
#pragma unroll
        for (int mt = 0; mt < 2; mt++)
#pragma unroll
            for (int nt = 0; nt < 4; nt++)
                mma16816(c[mt][nt], a[mt], bq[nt >> 1][(nt & 1) * 2],
                         bq[nt >> 1][(nt & 1) * 2 + 1]);
    }

    // epilogue: z = half(acc + bias); zero agg
    int r_in = lane >> 2, col_in = 2 * (lane & 3);
#pragma unroll
    for (int mt = 0; mt < 2; mt++) {
#pragma unroll
        for (int nt = 0; nt < 4; nt++) {
            int row = row0 + wm * 32 + mt * 16 + r_in;
            int col = wn * 32 + nt * 8 + col_in;
            float bb0 = b_s[col], bb1 = b_s[col + 1];
            if (row < N_NODES)
                *(__half2*)(g_z + (size_t)row * DPAD + col) =
                    __floats2half2_rn(c[mt][nt][0] + bb0, c[mt][nt][1] + bb1);
            if (row + 8 < N_NODES)
                *(__half2*)(g_z + (size_t)(row + 8) * DPAD + col) =
                    __floats2half2_rn(c[mt][nt][2] + bb0, c[mt][nt][3] + bb1);
        }
    }
    {
        uint4 zz = make_uint4(0u, 0u, 0u, 0u);
        uint4* a4 = (uint4*)(g_agg + (size_t)row0 * DPAD);
        for (int j = tid; j < GR * 16; j += 256) {
            int row = row0 + (j >> 4);
            if (row < N_NODES) a4[j] = zz;
        }
    }
}

// Warp processes 8 edges: lanes 0-7 load metadata, shuffle-broadcast, then
// 8 overlapped 256B fp16 row loads (MLP=8) followed by 8 fp16x2 v2 reductions.
// NE % 8 == 0, grid sized exactly -> no bounds checks.
__global__ void k_edge(const int* __restrict__ src, const int* __restrict__ dst,
                       const float* __restrict__ wt) {
    int warp = (blockIdx.x * blockDim.x + threadIdx.x) >> 5;
    int lane = threadIdx.x & 31;
    int e0 = warp * 8;

    int s = 0, d = 0;
    float w = 0.f;
    if (lane < 8) {
        s = src[e0 + lane];
        d = dst[e0 + lane];
        w = wt[e0 + lane];
    }

    const uint2* z2 = (const uint2*)g_z;
    uint2 v[8];
#pragma unroll
    for (int i = 0; i < 8; i++) {
        int si = __shfl_sync(0xffffffffu, s, i);
        v[i] = z2[(size_t)si * 32 + lane];
    }
#pragma unroll
    for (int i = 0; i < 8; i++) {
        int   di = __shfl_sync(0xffffffffu, d, i);
        float wi = __shfl_sync(0xffffffffu, w, i);
        float2 f0 = __half22float2(*(const __half2*)&v[i].x);
        float2 f1 = __half22float2(*(const __half2*)&v[i].y);
        __half2 m0 = __floats2half2_rn(f0.x * wi, f0.y * wi);
        __half2 m1 = __floats2half2_rn(f1.x * wi, f1.y * wi);
        __half* a = g_agg + (size_t)di * DPAD + 4 * lane;
        asm volatile("red.global.add.noftz.v2.f16x2 [%0], {%1,%2};"
                     :: "l"(a), "r"(*(unsigned*)&m0), "r"(*(unsigned*)&m1)
                     : "memory");
    }
}

// h2 = relu(agg2) + h1;  out = expmap0(h2)
__global__ void k_final(float* __restrict__ out) {
    int warp = (blockIdx.x * blockDim.x + threadIdx.x) >> 5;
    int lane = threadIdx.x & 31;
    if (warp >= N_NODES) return;
    float v[4];
    float n2 = 0.f;
#pragma unroll
    for (int j = 0; j < 4; j++) {
        int c = lane + 32 * j;
        float a  = __half2float(g_agg[warp * DPAD + c]);
        float hv = __half2float(g_h16[warp * DPAD + c]);
        v[j] = (c < DS) ? (fmaxf(a, 0.f) + hv) : 0.f;
        n2 += v[j] * v[j];
    }
    n2 = warp_sum(n2);
    float n = fmaxf(sqrtf(n2), EPSF);
    float t = coshf(n);
    float f = sinhf(n) / n;
    if (lane == 0) out[warp * DPAD] = t;
#pragma unroll
    for (int j = 0; j < 4; j++) {
        int c = lane + 32 * j;
        if (c < DS) out[warp * DPAD + 1 + c] = f * v[j];
    }
}

extern "C" void kernel_launch(void* const* d_in, const int* in_sizes, int n_in,
                              void* d_out, int out_size) {
    const float* x  = (const float*)d_in[0];
    const float* W1 = (const float*)d_in[1];
    const float* b1 = (const float*)d_in[2];
    const float* W2 = (const float*)d_in[3];
    const float* b2 = (const float*)d_in[4];
    const int*   es = (const int*)d_in[5];
    const int*   ed = (const int*)d_in[6];
    const float* ew = (const float*)d_in[7];
    float* out = (float*)d_out;

    const int smem_bytes = (DPAD * HSTRIDE + GR * HSTRIDE) * 2 + DPAD * 4;  // 52736
    cudaFuncSetAttribute(k_gemm, cudaFuncAttributeMaxDynamicSharedMemorySize, smem_bytes);

    int gemm_blocks = (N_NODES + GR - 1) / GR;       // 782
    int edge_blocks = (NE / 8) / 8;                  // 12500
    int row_blocks  = (N_NODES * 32 + 255) / 256;    // 6250
    int prep_total  = 2 * DPAD * DPAD + N_NODES * DPAD;

    k_prep<<<(prep_total + 255) / 256, 256>>>(W1, W2, x);

    k_gemm<<<gemm_blocks, 256, smem_bytes>>>(b1, 0);
    k_edge<<<edge_blocks, 256>>>(es, ed, ew);

    k_gemm<<<gemm_blocks, 256, smem_bytes>>>(b2, 1);
    k_edge<<<edge_blocks, 256>>>(es, ed, ew);

    k_final<<<row_blocks, 256>>>(out);
}

// round 15
// speedup vs baseline: 1.5405x; 1.0120x over previous
#include <cuda_runtime.h>
#include <cuda_fp16.h>
#include <cstdint>

#define N_NODES 50000
#define DS 127
#define DPAD 128
#define NE 800000
#define EPSF 1e-7f
#define GR 64        // rows per tile
#define TILES 2      // tiles per block
#define HSTRIDE 136  // smem stride in halves (conflict-free ldmatrix)

// g_x16: x as fp16, padded [N][128], pad col 0
// g_h16: h1 = relu(agg1)+x as fp16 (layer-2 prologue), pad col 0
// g_z  : gemm output fp16; pad col 0
// g_agg: fp16 atomic accumulation target; pad col garbage, never read
// g_Wt : W1,W2 as fp16, n-major [n][k] 128x128 each, pads zero
__device__ __align__(16) __half g_x16[N_NODES * DPAD];
__device__ __align__(16) __half g_h16[N_NODES * DPAD];
__device__ __align__(16) __half g_z[N_NODES * DPAD];
__device__ __align__(16) __half g_agg[N_NODES * DPAD];
__device__ __align__(16) __half g_Wt[2 * DPAD * DPAD];

__device__ __forceinline__ float warp_sum(float v) {
#pragma unroll
    for (int o = 16; o; o >>= 1) v += __shfl_xor_sync(0xffffffffu, v, o);
    return v;
}

__device__ __forceinline__ void ldsm4(uint32_t* r, uint32_t addr) {
    asm volatile("ldmatrix.sync.aligned.m8n8.x4.shared.b16 {%0,%1,%2,%3}, [%4];"
                 : "=r"(r[0]), "=r"(r[1]), "=r"(r[2]), "=r"(r[3]) : "r"(addr));
}

__device__ __forceinline__ void mma16816(float* c, const uint32_t* a,
                                         uint32_t b0, uint32_t b1) {
    asm volatile(
        "mma.sync.aligned.m16n8k16.row.col.f32.f16.f16.f32 "
        "{%0,%1,%2,%3}, {%4,%5,%6,%7}, {%8,%9}, {%0,%1,%2,%3};"
        : "+f"(c[0]), "+f"(c[1]), "+f"(c[2]), "+f"(c[3])
        : "r"(a[0]), "r"(a[1]), "r"(a[2]), "r"(a[3]), "r"(b0), "r"(b1));
}

__device__ __forceinline__ void cp16(uint32_t smem_addr, const void* gptr) {
    asm volatile("cp.async.cg.shared.global [%0], [%1], 16;"
                 :: "r"(smem_addr), "l"(gptr));
}

// Merged prep: W1,W2 -> g_Wt (fp16 n-major, zero pads), x -> g_x16 (fp16 padded)
__global__ void k_prep(const float* __restrict__ W1, const float* __restrict__ W2,
                       const float* __restrict__ x) {
    int idx = blockIdx.x * 256 + threadIdx.x;
    const int WTOT = 2 * DPAD * DPAD;
    if (idx < WTOT) {
        int l = idx >> 14, rem = idx & 16383, n = rem >> 7, k = rem & 127;
        const float* W = l ? W2 : W1;
        float v = (k < DS && n < DS) ? W[k * DS + n] : 0.f;
        g_Wt[idx] = __float2half(v);
    }
    int xi = idx - WTOT;
    if (xi >= 0 && xi < N_NODES * DPAD) {
        int row = xi >> 7, c = xi & 127;
        g_x16[xi] = __float2half((c < DS) ? x[row * DS + c] : 0.f);
    }
}

// Fill one 64-row h tile (base smem addr ht_base / generic ptr Ht).
// layer==0: cp.async copy from g_x16 (caller commits/waits).
// layer==1: h = relu(agg)+x16, stored to smem AND g_h16.
__device__ __forceinline__ void build_h(__half* Ht, uint32_t ht_base,
                                        int row0, int layer, int tid) {
    if (layer == 0) {
        for (int j = tid; j < GR * 16; j += 256) {
            int r = j >> 4, ch = j & 15;
            int row = row0 + r;
            if (row < N_NODES) {
                cp16(ht_base + (uint32_t)(r * HSTRIDE + ch * 8) * 2,
                     (const uint4*)(g_x16 + (size_t)row * DPAD) + ch);
            } else {
                *(uint4*)(Ht + r * HSTRIDE + ch * 8) = make_uint4(0u, 0u, 0u, 0u);
            }
        }
    } else {
        for (int j = tid; j < GR * 16; j += 256) {
            int r = j >> 4, ch = j & 15;
            int row = row0 + r;
            uint4 v = make_uint4(0u, 0u, 0u, 0u);
            if (row < N_NODES) {
                v = ((const uint4*)(g_x16 + (size_t)row * DPAD))[ch];
                uint4 a = ((const uint4*)(g_agg + (size_t)row * DPAD))[ch];
                __half2* vh = (__half2*)&v;
                __half2* ah = (__half2*)&a;
#pragma unroll
                for (int i = 0; i < 4; i++) {
                    float2 xf = __half22float2(vh[i]);
                    float2 af = __half22float2(ah[i]);
                    vh[i] = __floats2half2_rn(xf.x + fmaxf(af.x, 0.f),
                                              xf.y + fmaxf(af.y, 0.f));
                }
                ((uint4*)(g_h16 + (size_t)row * DPAD))[ch] = v;
            }
            *(uint4*)(Ht + r * HSTRIDE + ch * 8) = v;
        }
    }
}

// One 64-row tile: mma from Ht (smem base ht_base) + epilogue (z store, agg zero).
__device__ __forceinline__ void mma_tile(uint32_t ht_base, uint32_t wt_s,
                                         const float* b_s, int row0, int tid) {
    int lane = tid & 31, wid = tid >> 5;
    int wm = wid >> 2, wn = wid & 3;

    uint32_t aaddr[2];
#pragma unroll
    for (int mt = 0; mt < 2; mt++) {
        int rowA = wm * 32 + mt * 16 + (lane & 15);
        int kA   = (lane >> 4) * 8;
        aaddr[mt] = ht_base + (uint32_t)(rowA * HSTRIDE + kA) * 2;
    }
    uint32_t baddr[2];
#pragma unroll
    for (int p = 0; p < 2; p++) {
        int rowB = wn * 32 + p * 16 + (lane >> 4) * 8 + (lane & 7);
        int kB   = ((lane >> 3) & 1) * 8;
        baddr[p] = wt_s + (uint32_t)(rowB * HSTRIDE + kB) * 2;
    }

    float c[2][4][4];
#pragma unroll
    for (int mt = 0; mt < 2; mt++)
#pragma unroll
        for (int nt = 0; nt < 4; nt++)
#pragma unroll
            for (int j = 0; j < 4; j++) c[mt][nt][j] = 0.f;

#pragma unroll
    for (int ks = 0; ks < 8; ks++) {
        uint32_t kb = (uint32_t)(ks * 16 * 2);
        uint32_t a[2][4], bq[2][4];
        ldsm4(a[0], aaddr[0] + kb);
        ldsm4(a[1], aaddr[1] + kb);
        ldsm4(bq[0], baddr[0] + kb);
        ldsm4(bq[1], baddr[1] + kb);
#pragma unroll
        for (int mt = 0; mt < 2; mt++)
#pragma unroll
            for (int nt = 0; nt < 4; nt++)
                mma16816(c[mt][nt], a[mt], bq[nt >> 1][(nt & 1) * 2],
                         bq[nt >> 1][(nt & 1) * 2 + 1]);
    }

    int r_in = lane >> 2, col_in = 2 * (lane & 3);
#pragma unroll
    for (int mt = 0; mt < 2; mt++) {
#pragma unroll
        for (int nt = 0; nt < 4; nt++) {
            int row = row0 + wm * 32 + mt * 16 + r_in;
            int col = wn * 32 + nt * 8 + col_in;
            float bb0 = b_s[col], bb1 = b_s[col + 1];
            if (row < N_NODES)
                *(__half2*)(g_z + (size_t)row * DPAD + col) =
                    __floats2half2_rn(c[mt][nt][0] + bb0, c[mt][nt][1] + bb1);
            if (row + 8 < N_NODES)
                *(__half2*)(g_z + (size_t)(row + 8) * DPAD + col) =
                    __floats2half2_rn(c[mt][nt][2] + bb0, c[mt][nt][3] + bb1);
        }
    }
    {
        uint4 zz = make_uint4(0u, 0u, 0u, 0u);
        uint4* a4 = (uint4*)(g_agg + (size_t)row0 * DPAD);
        for (int j = tid; j < GR * 16; j += 256) {
            int row = row0 + (j >> 4);
            if (row < N_NODES) a4[j] = zz;
        }
    }
}

// 128 rows per block as 2 x 64-row tiles; W loaded once; h double-buffered.
// Single wave: 391 blocks <= 444 resident at 3 CTAs/SM.
__global__ void __launch_bounds__(256, 3)
k_gemm(const float* __restrict__ b, int layer) {
    extern __shared__ __align__(16) char smem_raw[];
    __half* Wt  = (__half*)smem_raw;                   // [128][136]
    __half* Ht0 = Wt + DPAD * HSTRIDE;                 // [64][136]
    __half* Ht1 = Ht0 + GR * HSTRIDE;                  // [64][136]
    float*  b_s = (float*)(Ht1 + GR * HSTRIDE);        // [128]
    int tid  = threadIdx.x;
    int row0 = blockIdx.x * (GR * TILES);

    uint32_t wt_s  = (uint32_t)__cvta_generic_to_shared(Wt);
    uint32_t ht0_s = (uint32_t)__cvta_generic_to_shared(Ht0);
    uint32_t ht1_s = (uint32_t)__cvta_generic_to_shared(Ht1);

    // W fill via cp.async (once per block)
    {
        const uint4* src = (const uint4*)(g_Wt + layer * DPAD * DPAD);
        for (int j = tid; j < 2048; j += 256) {
            int n = j >> 4, kc = j & 15;
            cp16(wt_s + (uint32_t)(n * HSTRIDE + kc * 8) * 2, src + j);
        }
    }
    if (tid < DPAD) b_s[tid] = (tid < DS) ? b[tid] : 0.f;

    // h tile 0
    build_h(Ht0, ht0_s, row0, layer, tid);
    asm volatile("cp.async.commit_group;");
    asm volatile("cp.async.wait_group 0;");
    __syncthreads();

    // h tile 1 issued before mma0 (cp.async in flight during tile-0 compute)
    build_h(Ht1, ht1_s, row0 + GR, layer, tid);
    asm volatile("cp.async.commit_group;");

    mma_tile(ht0_s, wt_s, b_s, row0, tid);

    asm volatile("cp.async.wait_group 0;");
    __syncthreads();

    mma_tile(ht1_s, wt_s, b_s, row0 + GR, tid);
}

// Warp processes 8 edges: lanes 0-7 load metadata, shuffle-broadcast, then
// 8 overlapped 256B fp16 row loads (MLP=8) followed by 8 fp16x2 v2 reductions.
__global__ void k_edge(const int* __restrict__ src, const int* __restrict__ dst,
                       const float* __restrict__ wt) {
    int warp = (blockIdx.x * blockDim.x + threadIdx.x) >> 5;
    int lane = threadIdx.x & 31;
    int e0 = warp * 8;

    int s = 0, d = 0;
    float w = 0.f;
    if (lane < 8) {
        s = src[e0 + lane];
        d = dst[e0 + lane];
        w = wt[e0 + lane];
    }

    const uint2* z2 = (const uint2*)g_z;
    uint2 v[8];
#pragma unroll
    for (int i = 0; i < 8; i++) {
        int si = __shfl_sync(0xffffffffu, s, i);
        v[i] = z2[(size_t)si * 32 + lane];
    }
#pragma unroll
    for (int i = 0; i < 8; i++) {
        int   di = __shfl_sync(0xffffffffu, d, i);
        float wi = __shfl_sync(0xffffffffu, w, i);
        float2 f0 = __half22float2(*(const __half2*)&v[i].x);
        float2 f1 = __half22float2(*(const __half2*)&v[i].y);
        __half2 m0 = __floats2half2_rn(f0.x * wi, f0.y * wi);
        __half2 m1 = __floats2half2_rn(f1.x * wi, f1.y * wi);
        __half* a = g_agg + (size_t)di * DPAD + 4 * lane;
        asm volatile("red.global.add.noftz.v2.f16x2 [%0], {%1,%2};"
                     :: "l"(a), "r"(*(unsigned*)&m0), "r"(*(unsigned*)&m1)
                     : "memory");
    }
}

// h2 = relu(agg2) + h1;  out = expmap0(h2)
__global__ void k_final(float* __restrict__ out) {
    int warp = (blockIdx.x * blockDim.x + threadIdx.x) >> 5;
    int lane = threadIdx.x & 31;
    if (warp >= N_NODES) return;
    float v[4];
    float n2 = 0.f;
#pragma unroll
    for (int j = 0; j < 4; j++) {
        int c = lane + 32 * j;
        float a  = __half2float(g_agg[warp * DPAD + c]);
        float hv = __half2float(g_h16[warp * DPAD + c]);
        v[j] = (c < DS) ? (fmaxf(a, 0.f) + hv) : 0.f;
        n2 += v[j] * v[j];
    }
    n2 = warp_sum(n2);
    float n = fmaxf(sqrtf(n2), EPSF);
    float t = coshf(n);
    float f = sinhf(n) / n;
    if (lane == 0) out[warp * DPAD] = t;
#pragma unroll
    for (int j = 0; j < 4; j++) {
        int c = lane + 32 * j;
        if (c < DS) out[warp * DPAD + 1 + c] = f * v[j];
    }
}

extern "C" void kernel_launch(void* const* d_in, const int* in_sizes, int n_in,
                              void* d_out, int out_size) {
    const float* x  = (const float*)d_in[0];
    const float* W1 = (const float*)d_in[1];
    const float* b1 = (const float*)d_in[2];
    const float* W2 = (const float*)d_in[3];
    const float* b2 = (const float*)d_in[4];
    const int*   es = (const int*)d_in[5];
    const int*   ed = (const int*)d_in[6];
    const float* ew = (const float*)d_in[7];
    float* out = (float*)d_out;

    const int smem_bytes = (DPAD * HSTRIDE + 2 * GR * HSTRIDE) * 2 + DPAD * 4;  // 70144
    cudaFuncSetAttribute(k_gemm, cudaFuncAttributeMaxDynamicSharedMemorySize, smem_bytes);

    int gemm_blocks = (N_NODES + GR * TILES - 1) / (GR * TILES);  // 391
    int edge_blocks = (NE / 8) / 8;                               // 12500
    int row_blocks  = (N_NODES * 32 + 255) / 256;                 // 6250
    int prep_total  = 2 * DPAD * DPAD + N_NODES * DPAD;

    k_prep<<<(prep_total + 255) / 256, 256>>>(W1, W2, x);

    k_gemm<<<gemm_blocks, 256, smem_bytes>>>(b1, 0);
    k_edge<<<edge_blocks, 256>>>(es, ed, ew);

    k_gemm<<<gemm_blocks, 256, smem_bytes>>>(b2, 1);
    k_edge<<<edge_blocks, 256>>>(es, ed, ew);

    k_final<<<row_blocks, 256>>>(out);
}